// round 16
// baseline (speedup 1.0000x reference)
#include <cuda_runtime.h>
#include <cuda_fp16.h>
#include <cstdint>

// GraphConv, 2-kernel pipeline:
//  K1 proj: pf = fp16( feats @ Wf^T ) via HMMA m16n8k16. PERSISTENT +
//           SOFTWARE-PIPELINED: 512 blocks x 2 tiles, next tile's coalesced
//           LDGs issued before current tile's MMA (hides DRAM latency).
//  K2 gather: out = relu( inv*( sum_{n valid} pf[idx_n] + srel.W_rel ) + b )
//           (unchanged R15: predicated loads, interleaved HADD2 — frozen)
// Shapes fixed: B=8, P=K=16384, N=16, IN=64, REL=3, OUT=64.

#define LOG2_K 14
#define ROWS_TOTAL (8 * 16384)

__device__ __align__(16) __half g_pf[(size_t)ROWS_TOTAL * 64];

__device__ __forceinline__ uint32_t smem_u32(const void* p) {
    uint32_t a;
    asm("{ .reg .u64 t; cvta.to.shared.u64 t, %1; cvt.u32.u64 %0, t; }"
        : "=r"(a) : "l"(p));
    return a;
}

// ---------------------------------------------------------------------------
// Kernel 1: persistent, software-pipelined HMMA proj.
// ---------------------------------------------------------------------------
#define A_STRIDE 72
#define W_STRIDE 66
#define TILES (ROWS_TOTAL / 128)   // 1024
#define PROJ_BLOCKS 512            // 2 tiles per block

__global__ __launch_bounds__(256)
void proj_kernel(const float* __restrict__ feats,
                 const float* __restrict__ W,     // [64][67]
                 __half*      __restrict__ pf)
{
    __shared__ __half a_s[128 * A_STRIDE];
    __shared__ __half w_s[64 * W_STRIDE];

    const int tid = threadIdx.x;

    for (int i = tid; i < 64 * 64; i += 256) {
        int o = i >> 6, k = i & 63;
        w_s[o * W_STRIDE + k] = __float2half(W[o * 67 + k]);
    }

    const int warp = tid >> 5;
    const int lane = tid & 31;
    const int g    = lane >> 2;
    const int t4   = lane & 3;

    const uint32_t a_base = smem_u32(a_s)
        + ((warp * 16 + (lane & 15)) * A_STRIDE + (lane >> 4) * 8) * 2;
    const __half* wrow = w_s + g * W_STRIDE + t4 * 2;

    const float4* fbase = reinterpret_cast<const float4*>(feats);

    // prologue: load first tile (coalesced: lane-consecutive float4s)
    float4 v[8];
    {
        const float4* fg = fbase + (size_t)blockIdx.x * (128 * 16);
        #pragma unroll
        for (int i = 0; i < 8; i++) v[i] = fg[i * 256 + tid];
    }

    for (int tile = blockIdx.x; tile < TILES; tile += PROJ_BLOCKS) {
        // ---- stage current tile into a_s ----
        __syncthreads();   // prior iteration's a_s reads complete
        #pragma unroll
        for (int i = 0; i < 8; i++) {
            const int chunk = i * 256 + tid;
            const int row   = chunk >> 4;
            const int c4    = chunk & 15;
            __half2* dst = reinterpret_cast<__half2*>(
                a_s + row * A_STRIDE + c4 * 4);
            dst[0] = __floats2half2_rn(v[i].x, v[i].y);
            dst[1] = __floats2half2_rn(v[i].z, v[i].w);
        }
        __syncthreads();

        // ---- prefetch next tile (overlaps with MMA + epilogue below) ----
        float4 vn[8];
        const int next = tile + PROJ_BLOCKS;
        if (next < TILES) {
            const float4* fg = fbase + (size_t)next * (128 * 16);
            #pragma unroll
            for (int i = 0; i < 8; i++) vn[i] = fg[i * 256 + tid];
        }

        // ---- MMA ----
        float d[8][4];
        #pragma unroll
        for (int nt = 0; nt < 8; nt++)
            d[nt][0] = d[nt][1] = d[nt][2] = d[nt][3] = 0.0f;

        #pragma unroll
        for (int kt = 0; kt < 4; kt++) {
            uint32_t a0, a1, a2, a3;
            asm volatile(
                "ldmatrix.sync.aligned.m8n8.x4.shared.b16 {%0,%1,%2,%3}, [%4];"
                : "=r"(a0), "=r"(a1), "=r"(a2), "=r"(a3)
                : "r"(a_base + kt * 32));
            #pragma unroll
            for (int nt = 0; nt < 8; nt++) {
                const __half* wp = wrow + nt * 8 * W_STRIDE + kt * 16;
                const uint32_t b0 = *reinterpret_cast<const uint32_t*>(wp);
                const uint32_t b1 = *reinterpret_cast<const uint32_t*>(wp + 8);
                asm volatile(
                    "mma.sync.aligned.m16n8k16.row.col.f32.f16.f16.f32 "
                    "{%0,%1,%2,%3}, {%4,%5,%6,%7}, {%8,%9}, {%0,%1,%2,%3};"
                    : "+f"(d[nt][0]), "+f"(d[nt][1]), "+f"(d[nt][2]), "+f"(d[nt][3])
                    : "r"(a0), "r"(a1), "r"(a2), "r"(a3), "r"(b0), "r"(b1));
            }
        }

        // ---- epilogue: stage through a_s, coalesced STG.128 ----
        __syncthreads();   // ldmatrix reads of a_s complete
        const int r0w = warp * 16 + g;
        #pragma unroll
        for (int nt = 0; nt < 8; nt++) {
            const int col = nt * 8 + t4 * 2;
            *reinterpret_cast<__half2*>(a_s + r0w * A_STRIDE + col)
                = __floats2half2_rn(d[nt][0], d[nt][1]);
            *reinterpret_cast<__half2*>(a_s + (r0w + 8) * A_STRIDE + col)
                = __floats2half2_rn(d[nt][2], d[nt][3]);
        }
        __syncthreads();

        uint4* po = reinterpret_cast<uint4*>(pf + (size_t)tile * (128 * 64));
        #pragma unroll
        for (int j = 0; j < 4; j++) {
            const int chunk = j * 256 + tid;
            const int row   = chunk >> 3;
            const int c     = chunk & 7;
            po[chunk] = *reinterpret_cast<const uint4*>(
                a_s + row * A_STRIDE + c * 8);
        }

        if (next < TILES) {
            #pragma unroll
            for (int i = 0; i < 8; i++) v[i] = vn[i];
        }
    }
}

// ---------------------------------------------------------------------------
// Kernel 2: gather-sum (R15, frozen): predicated loads + interleaved HADD2.
// ---------------------------------------------------------------------------
#define THREADS 256
#define ROWS_PER_BLOCK 32   // 8 warps * 4 rows

__device__ __forceinline__ uint4 pld(const uint4* a, int v) {
    uint4 h;
    asm volatile(
        "{\n\t"
        ".reg .pred p;\n\t"
        "setp.ne.s32 p, %5, 0;\n\t"
        "mov.u32 %0, 0;\n\t"
        "mov.u32 %1, 0;\n\t"
        "mov.u32 %2, 0;\n\t"
        "mov.u32 %3, 0;\n\t"
        "@p ld.global.nc.v4.u32 {%0,%1,%2,%3}, [%4];\n\t"
        "}"
        : "=r"(h.x), "=r"(h.y), "=r"(h.z), "=r"(h.w)
        : "l"(a), "r"(v));
    return h;
}

__device__ __forceinline__ uint4 hadd4(const uint4 x, const uint4 y) {
    uint4 r;
    __half2 a, b;
    a = __hadd2(*reinterpret_cast<const __half2*>(&x.x),
                *reinterpret_cast<const __half2*>(&y.x));
    r.x = *reinterpret_cast<uint32_t*>(&a);
    b = __hadd2(*reinterpret_cast<const __half2*>(&x.y),
                *reinterpret_cast<const __half2*>(&y.y));
    r.y = *reinterpret_cast<uint32_t*>(&b);
    a = __hadd2(*reinterpret_cast<const __half2*>(&x.z),
                *reinterpret_cast<const __half2*>(&y.z));
    r.z = *reinterpret_cast<uint32_t*>(&a);
    b = __hadd2(*reinterpret_cast<const __half2*>(&x.w),
                *reinterpret_cast<const __half2*>(&y.w));
    r.w = *reinterpret_cast<uint32_t*>(&b);
    return r;
}

__global__ __launch_bounds__(THREADS, 4)
void gather_kernel(const __half* __restrict__ pf,
                   const int*    __restrict__ n_idxs,
                   const int*    __restrict__ nvalid,
                   const float*  __restrict__ nrel,
                   const float*  __restrict__ W,     // [64][67]
                   const float*  __restrict__ bias,
                   float*        __restrict__ out,
                   int rows_total)
{
    __shared__ float wr_s[3 * 64];
    __shared__ float b_s[64];

    const int tid = threadIdx.x;
    for (int i = tid; i < 192; i += THREADS) {
        int jc = i >> 6, o = i & 63;
        wr_s[i] = W[o * 67 + 64 + jc];
    }
    if (tid < 64) b_s[tid] = bias[tid];
    __syncthreads();

    const int warp = tid >> 5;
    const int lane = tid & 31;
    const int q    = lane >> 3;
    const int t    = lane & 7;

    const int row = blockIdx.x * ROWS_PER_BLOCK + warp * 4 + q;
    if (row >= rows_total) return;
    const int base = (row >> LOG2_K) << LOG2_K;

    const int4* ip = reinterpret_cast<const int4*>(n_idxs + row * 16);
    const int4* vp = reinterpret_cast<const int4*>(nvalid + row * 16);
    const int4 ia = ip[0], ib = ip[1], ic = ip[2], id = ip[3];
    const int4 va = vp[0], vb = vp[1], vc = vp[2], vd = vp[3];

    const float2* rp2 = reinterpret_cast<const float2*>(nrel + (size_t)row * 48);
    const float2 ra = rp2[3 * t + 0];
    const float2 rb = rp2[3 * t + 1];
    const float2 rc = rp2[3 * t + 2];
    const int2 vpair = *reinterpret_cast<const int2*>(nvalid + row * 16 + 2 * t);

    const uint4* pg = reinterpret_cast<const uint4*>(pf);
    #define GADDR(I) (pg + ((size_t)(base + (I)) * 8 + t))

    uint4 h0 = pld(GADDR(ia.x), va.x);
    uint4 h1 = pld(GADDR(ia.y), va.y);
    uint4 h2 = pld(GADDR(ia.z), va.z);
    uint4 h3 = pld(GADDR(ia.w), va.w);
    uint4 h4 = pld(GADDR(ib.x), vb.x);
    uint4 h5 = pld(GADDR(ib.y), vb.y);
    uint4 h6 = pld(GADDR(ib.z), vb.z);
    uint4 h7 = pld(GADDR(ib.w), vb.w);

    uint4 s0 = hadd4(h0, h1);
    h0 = pld(GADDR(ic.x), vc.x);
    h1 = pld(GADDR(ic.y), vc.y);
    uint4 s1 = hadd4(h2, h3);
    h2 = pld(GADDR(ic.z), vc.z);
    h3 = pld(GADDR(ic.w), vc.w);
    uint4 s2 = hadd4(h4, h5);
    h4 = pld(GADDR(id.x), vd.x);
    h5 = pld(GADDR(id.y), vd.y);
    uint4 s3 = hadd4(h6, h7);
    h6 = pld(GADDR(id.z), vd.z);
    h7 = pld(GADDR(id.w), vd.w);

    const float vfa = (float)vpair.x, vfb = (float)vpair.y;
    float r0  = ra.x * vfa + rb.y * vfb;
    float r1  = ra.y * vfa + rc.x * vfb;
    float r2  = rb.x * vfa + rc.y * vfb;
    float cnt = vfa + vfb;
    #pragma unroll
    for (int m = 1; m < 8; m <<= 1) {
        r0  += __shfl_xor_sync(0xffffffffu, r0,  m);
        r1  += __shfl_xor_sync(0xffffffffu, r1,  m);
        r2  += __shfl_xor_sync(0xffffffffu, r2,  m);
        cnt += __shfl_xor_sync(0xffffffffu, cnt, m);
    }
    const float inv = (cnt > 0.0f) ? (1.0f / cnt) : 0.0f;

    s0 = hadd4(s0, s2);
    s1 = hadd4(s1, s3);
    uint4 s4 = hadd4(h0, h1);
    uint4 s5 = hadd4(h2, h3);
    uint4 s6 = hadd4(h4, h5);
    uint4 s7 = hadd4(h6, h7);
    s4 = hadd4(s4, s6);
    s5 = hadd4(s5, s7);

    float a0 = 0.f, a1 = 0.f, a2 = 0.f, a3 = 0.f;
    float a4 = 0.f, a5 = 0.f, a6 = 0.f, a7 = 0.f;
    #define ACCUM(H) do {                                                      \
        const float2 f0 = __half22float2(*reinterpret_cast<const __half2*>(&(H).x)); \
        const float2 f1 = __half22float2(*reinterpret_cast<const __half2*>(&(H).y)); \
        const float2 f2 = __half22float2(*reinterpret_cast<const __half2*>(&(H).z)); \
        const float2 f3 = __half22float2(*reinterpret_cast<const __half2*>(&(H).w)); \
        a0 += f0.x; a1 += f0.y; a2 += f1.x; a3 += f1.y;                        \
        a4 += f2.x; a5 += f2.y; a6 += f3.x; a7 += f3.y;                        \
    } while (0)
    ACCUM(s0); ACCUM(s1); ACCUM(s4); ACCUM(s5);
    #undef ACCUM

    const float4* wr4 = reinterpret_cast<const float4*>(wr_s);
    const float4 w0a = wr4[0 * 16 + t * 2], w0b = wr4[0 * 16 + t * 2 + 1];
    const float4 w1a = wr4[1 * 16 + t * 2], w1b = wr4[1 * 16 + t * 2 + 1];
    const float4 w2a = wr4[2 * 16 + t * 2], w2b = wr4[2 * 16 + t * 2 + 1];
    const float4 bga = reinterpret_cast<const float4*>(b_s)[t * 2];
    const float4 bgb = reinterpret_cast<const float4*>(b_s)[t * 2 + 1];

    a0 = fmaf(r0, w0a.x, a0); a1 = fmaf(r0, w0a.y, a1);
    a2 = fmaf(r0, w0a.z, a2); a3 = fmaf(r0, w0a.w, a3);
    a4 = fmaf(r0, w0b.x, a4); a5 = fmaf(r0, w0b.y, a5);
    a6 = fmaf(r0, w0b.z, a6); a7 = fmaf(r0, w0b.w, a7);
    a0 = fmaf(r1, w1a.x, a0); a1 = fmaf(r1, w1a.y, a1);
    a2 = fmaf(r1, w1a.z, a2); a3 = fmaf(r1, w1a.w, a3);
    a4 = fmaf(r1, w1b.x, a4); a5 = fmaf(r1, w1b.y, a5);
    a6 = fmaf(r1, w1b.z, a6); a7 = fmaf(r1, w1b.w, a7);
    a0 = fmaf(r2, w2a.x, a0); a1 = fmaf(r2, w2a.y, a1);
    a2 = fmaf(r2, w2a.z, a2); a3 = fmaf(r2, w2a.w, a3);
    a4 = fmaf(r2, w2b.x, a4); a5 = fmaf(r2, w2b.y, a5);
    a6 = fmaf(r2, w2b.z, a6); a7 = fmaf(r2, w2b.w, a7);

    float4 resA, resB;
    resA.x = fmaxf(fmaf(a0, inv, bga.x), 0.0f);
    resA.y = fmaxf(fmaf(a1, inv, bga.y), 0.0f);
    resA.z = fmaxf(fmaf(a2, inv, bga.z), 0.0f);
    resA.w = fmaxf(fmaf(a3, inv, bga.w), 0.0f);
    resB.x = fmaxf(fmaf(a4, inv, bgb.x), 0.0f);
    resB.y = fmaxf(fmaf(a5, inv, bgb.y), 0.0f);
    resB.z = fmaxf(fmaf(a6, inv, bgb.z), 0.0f);
    resB.w = fmaxf(fmaf(a7, inv, bgb.w), 0.0f);

    float4* op = reinterpret_cast<float4*>(out) + (size_t)row * 16;
    op[t * 2]     = resA;
    op[t * 2 + 1] = resB;
}

extern "C" void kernel_launch(void* const* d_in, const int* in_sizes, int n_in,
                              void* d_out, int out_size)
{
    // metadata order: keys, points, feats, n_idxs, neighbor_rel,
    //                 neighbor_valid, W, b
    const float* feats  = (const float*)d_in[2];
    const int*   n_idxs = (const int*)  d_in[3];
    const float* nrel   = (const float*)d_in[4];
    const int*   nvalid = (const int*)  d_in[5];
    const float* W      = (const float*)d_in[6];
    const float* bias   = (const float*)d_in[7];
    float*       out    = (float*)d_out;

    const int rows_total = out_size / 64;   // 131072

    __half* pf = nullptr;
    cudaGetSymbolAddress((void**)&pf, g_pf);

    proj_kernel<<<PROJ_BLOCKS, 256>>>(feats, W, pf);

    const int grid = (rows_total + ROWS_PER_BLOCK - 1) / ROWS_PER_BLOCK;
    gather_kernel<<<grid, THREADS>>>(pf, n_idxs, nvalid, nrel,
                                     W, bias, out, rows_total);
}

// round 17
// speedup vs baseline: 1.0314x; 1.0314x over previous
#include <cuda_runtime.h>
#include <cuda_fp16.h>
#include <cstdint>

// GraphConv, 2-kernel pipeline with PDL overlap:
//  K1 proj: pf = fp16( feats @ Wf^T ) via HMMA m16n8k16 (R15 one-shot,
//           proven) + cudaTriggerProgrammaticLaunchCompletion per block.
//  K2 gather (PDL secondary): loads all proj-independent metadata FIRST,
//           then cudaGridDependencySynchronize(), then the pf gathers.
// Shapes fixed: B=8, P=K=16384, N=16, IN=64, REL=3, OUT=64.

#define LOG2_K 14
#define ROWS_TOTAL (8 * 16384)

__device__ __align__(16) __half g_pf[(size_t)ROWS_TOTAL * 64];

__device__ __forceinline__ uint32_t smem_u32(const void* p) {
    uint32_t a;
    asm("{ .reg .u64 t; cvta.to.shared.u64 t, %1; cvt.u32.u64 %0, t; }"
        : "=r"(a) : "l"(p));
    return a;
}

// ---------------------------------------------------------------------------
// Kernel 1: HMMA proj, one-shot, coalesced staging (R15) + PDL trigger.
// ---------------------------------------------------------------------------
#define A_STRIDE 72
#define W_STRIDE 66
#define TILES (ROWS_TOTAL / 128)   // 1024

__global__ __launch_bounds__(256)
void proj_kernel(const float* __restrict__ feats,
                 const float* __restrict__ W,     // [64][67]
                 __half*      __restrict__ pf)
{
    __shared__ __half a_s[128 * A_STRIDE];
    __shared__ __half w_s[64 * W_STRIDE];

    const int tid = threadIdx.x;

    for (int i = tid; i < 64 * 64; i += 256) {
        int o = i >> 6, k = i & 63;
        w_s[o * W_STRIDE + k] = __float2half(W[o * 67 + k]);
    }

    // coalesced feats staging: lane-consecutive float4 loads
    {
        const float4* fg = reinterpret_cast<const float4*>(feats)
                           + (size_t)blockIdx.x * (128 * 16);
        float4 v[8];
        #pragma unroll
        for (int i = 0; i < 8; i++) v[i] = fg[i * 256 + tid];

        #pragma unroll
        for (int i = 0; i < 8; i++) {
            const int chunk = i * 256 + tid;
            const int row   = chunk >> 4;
            const int c4    = chunk & 15;
            __half2* dst = reinterpret_cast<__half2*>(
                a_s + row * A_STRIDE + c4 * 4);
            dst[0] = __floats2half2_rn(v[i].x, v[i].y);
            dst[1] = __floats2half2_rn(v[i].z, v[i].w);
        }
    }
    __syncthreads();

    const int warp = tid >> 5;
    const int lane = tid & 31;
    const int g    = lane >> 2;
    const int t4   = lane & 3;

    float d[8][4];
    #pragma unroll
    for (int nt = 0; nt < 8; nt++)
        d[nt][0] = d[nt][1] = d[nt][2] = d[nt][3] = 0.0f;

    const uint32_t a_base = smem_u32(a_s)
        + ((warp * 16 + (lane & 15)) * A_STRIDE + (lane >> 4) * 8) * 2;
    const __half* wrow = w_s + g * W_STRIDE + t4 * 2;

    #pragma unroll
    for (int kt = 0; kt < 4; kt++) {
        uint32_t a0, a1, a2, a3;
        asm volatile(
            "ldmatrix.sync.aligned.m8n8.x4.shared.b16 {%0,%1,%2,%3}, [%4];"
            : "=r"(a0), "=r"(a1), "=r"(a2), "=r"(a3)
            : "r"(a_base + kt * 32));
        #pragma unroll
        for (int nt = 0; nt < 8; nt++) {
            const __half* wp = wrow + nt * 8 * W_STRIDE + kt * 16;
            const uint32_t b0 = *reinterpret_cast<const uint32_t*>(wp);
            const uint32_t b1 = *reinterpret_cast<const uint32_t*>(wp + 8);
            asm volatile(
                "mma.sync.aligned.m16n8k16.row.col.f32.f16.f16.f32 "
                "{%0,%1,%2,%3}, {%4,%5,%6,%7}, {%8,%9}, {%0,%1,%2,%3};"
                : "+f"(d[nt][0]), "+f"(d[nt][1]), "+f"(d[nt][2]), "+f"(d[nt][3])
                : "r"(a0), "r"(a1), "r"(a2), "r"(a3), "r"(b0), "r"(b1));
        }
    }

    __syncthreads();
    const int r0w = warp * 16 + g;
    #pragma unroll
    for (int nt = 0; nt < 8; nt++) {
        const int col = nt * 8 + t4 * 2;
        *reinterpret_cast<__half2*>(a_s + r0w * A_STRIDE + col)
            = __floats2half2_rn(d[nt][0], d[nt][1]);
        *reinterpret_cast<__half2*>(a_s + (r0w + 8) * A_STRIDE + col)
            = __floats2half2_rn(d[nt][2], d[nt][3]);
    }
    __syncthreads();

    uint4* po = reinterpret_cast<uint4*>(pf + (size_t)blockIdx.x * (128 * 64));
    #pragma unroll
    for (int j = 0; j < 4; j++) {
        const int chunk = j * 256 + tid;
        const int row   = chunk >> 3;
        const int c     = chunk & 7;
        po[chunk] = *reinterpret_cast<const uint4*>(
            a_s + row * A_STRIDE + c * 8);
    }

    // PDL: allow the dependent gather to begin launching
    cudaTriggerProgrammaticLaunchCompletion();
}

// ---------------------------------------------------------------------------
// Kernel 2: gather-sum (R15 body) as PDL secondary: metadata loads first,
// cudaGridDependencySynchronize(), then predicated pf gathers.
// ---------------------------------------------------------------------------
#define THREADS 256
#define ROWS_PER_BLOCK 32   // 8 warps * 4 rows

__device__ __forceinline__ uint4 pld(const uint4* a, int v) {
    uint4 h;
    asm volatile(
        "{\n\t"
        ".reg .pred p;\n\t"
        "setp.ne.s32 p, %5, 0;\n\t"
        "mov.u32 %0, 0;\n\t"
        "mov.u32 %1, 0;\n\t"
        "mov.u32 %2, 0;\n\t"
        "mov.u32 %3, 0;\n\t"
        "@p ld.global.nc.v4.u32 {%0,%1,%2,%3}, [%4];\n\t"
        "}"
        : "=r"(h.x), "=r"(h.y), "=r"(h.z), "=r"(h.w)
        : "l"(a), "r"(v));
    return h;
}

__device__ __forceinline__ uint4 hadd4(const uint4 x, const uint4 y) {
    uint4 r;
    __half2 a, b;
    a = __hadd2(*reinterpret_cast<const __half2*>(&x.x),
                *reinterpret_cast<const __half2*>(&y.x));
    r.x = *reinterpret_cast<uint32_t*>(&a);
    b = __hadd2(*reinterpret_cast<const __half2*>(&x.y),
                *reinterpret_cast<const __half2*>(&y.y));
    r.y = *reinterpret_cast<uint32_t*>(&b);
    a = __hadd2(*reinterpret_cast<const __half2*>(&x.z),
                *reinterpret_cast<const __half2*>(&y.z));
    r.z = *reinterpret_cast<uint32_t*>(&a);
    b = __hadd2(*reinterpret_cast<const __half2*>(&x.w),
                *reinterpret_cast<const __half2*>(&y.w));
    r.w = *reinterpret_cast<uint32_t*>(&b);
    return r;
}

__global__ __launch_bounds__(THREADS, 4)
void gather_kernel(const __half* __restrict__ pf,
                   const int*    __restrict__ n_idxs,
                   const int*    __restrict__ nvalid,
                   const float*  __restrict__ nrel,
                   const float*  __restrict__ W,     // [64][67]
                   const float*  __restrict__ bias,
                   float*        __restrict__ out,
                   int rows_total)
{
    __shared__ float wr_s[3 * 64];
    __shared__ float b_s[64];

    const int tid = threadIdx.x;
    for (int i = tid; i < 192; i += THREADS) {
        int jc = i >> 6, o = i & 63;
        wr_s[i] = W[o * 67 + 64 + jc];
    }
    if (tid < 64) b_s[tid] = bias[tid];
    __syncthreads();

    const int warp = tid >> 5;
    const int lane = tid & 31;
    const int q    = lane >> 3;
    const int t    = lane & 7;

    const int row = blockIdx.x * ROWS_PER_BLOCK + warp * 4 + q;
    if (row >= rows_total) {
        cudaGridDependencySynchronize();
        return;
    }
    const int base = (row >> LOG2_K) << LOG2_K;

    // ---- metadata loads (independent of proj output -> overlap its tail) ----
    const int4* ip = reinterpret_cast<const int4*>(n_idxs + row * 16);
    const int4* vp = reinterpret_cast<const int4*>(nvalid + row * 16);
    const int4 ia = ip[0], ib = ip[1], ic = ip[2], id = ip[3];
    const int4 va = vp[0], vb = vp[1], vc = vp[2], vd = vp[3];

    const float2* rp2 = reinterpret_cast<const float2*>(nrel + (size_t)row * 48);
    const float2 ra = rp2[3 * t + 0];
    const float2 rb = rp2[3 * t + 1];
    const float2 rc = rp2[3 * t + 2];
    const int2 vpair = *reinterpret_cast<const int2*>(nvalid + row * 16 + 2 * t);

    // rel/cnt reduction also pf-independent: do it before the dependency wait
    const float vfa = (float)vpair.x, vfb = (float)vpair.y;
    float r0  = ra.x * vfa + rb.y * vfb;
    float r1  = ra.y * vfa + rc.x * vfb;
    float r2  = rb.x * vfa + rc.y * vfb;
    float cnt = vfa + vfb;
    #pragma unroll
    for (int m = 1; m < 8; m <<= 1) {
        r0  += __shfl_xor_sync(0xffffffffu, r0,  m);
        r1  += __shfl_xor_sync(0xffffffffu, r1,  m);
        r2  += __shfl_xor_sync(0xffffffffu, r2,  m);
        cnt += __shfl_xor_sync(0xffffffffu, cnt, m);
    }
    const float inv = (cnt > 0.0f) ? (1.0f / cnt) : 0.0f;

    // ---- wait for proj's pf writes to be visible ----
    cudaGridDependencySynchronize();

    const uint4* pg = reinterpret_cast<const uint4*>(pf);
    #define GADDR(I) (pg + ((size_t)(base + (I)) * 8 + t))

    uint4 h0 = pld(GADDR(ia.x), va.x);
    uint4 h1 = pld(GADDR(ia.y), va.y);
    uint4 h2 = pld(GADDR(ia.z), va.z);
    uint4 h3 = pld(GADDR(ia.w), va.w);
    uint4 h4 = pld(GADDR(ib.x), vb.x);
    uint4 h5 = pld(GADDR(ib.y), vb.y);
    uint4 h6 = pld(GADDR(ib.z), vb.z);
    uint4 h7 = pld(GADDR(ib.w), vb.w);

    uint4 s0 = hadd4(h0, h1);
    h0 = pld(GADDR(ic.x), vc.x);
    h1 = pld(GADDR(ic.y), vc.y);
    uint4 s1 = hadd4(h2, h3);
    h2 = pld(GADDR(ic.z), vc.z);
    h3 = pld(GADDR(ic.w), vc.w);
    uint4 s2 = hadd4(h4, h5);
    h4 = pld(GADDR(id.x), vd.x);
    h5 = pld(GADDR(id.y), vd.y);
    uint4 s3 = hadd4(h6, h7);
    h6 = pld(GADDR(id.z), vd.z);
    h7 = pld(GADDR(id.w), vd.w);

    s0 = hadd4(s0, s2);
    s1 = hadd4(s1, s3);
    uint4 s4 = hadd4(h0, h1);
    uint4 s5 = hadd4(h2, h3);
    uint4 s6 = hadd4(h4, h5);
    uint4 s7 = hadd4(h6, h7);
    s4 = hadd4(s4, s6);
    s5 = hadd4(s5, s7);

    float a0 = 0.f, a1 = 0.f, a2 = 0.f, a3 = 0.f;
    float a4 = 0.f, a5 = 0.f, a6 = 0.f, a7 = 0.f;
    #define ACCUM(H) do {                                                      \
        const float2 f0 = __half22float2(*reinterpret_cast<const __half2*>(&(H).x)); \
        const float2 f1 = __half22float2(*reinterpret_cast<const __half2*>(&(H).y)); \
        const float2 f2 = __half22float2(*reinterpret_cast<const __half2*>(&(H).z)); \
        const float2 f3 = __half22float2(*reinterpret_cast<const __half2*>(&(H).w)); \
        a0 += f0.x; a1 += f0.y; a2 += f1.x; a3 += f1.y;                        \
        a4 += f2.x; a5 += f2.y; a6 += f3.x; a7 += f3.y;                        \
    } while (0)
    ACCUM(s0); ACCUM(s1); ACCUM(s4); ACCUM(s5);
    #undef ACCUM

    const float4* wr4 = reinterpret_cast<const float4*>(wr_s);
    const float4 w0a = wr4[0 * 16 + t * 2], w0b = wr4[0 * 16 + t * 2 + 1];
    const float4 w1a = wr4[1 * 16 + t * 2], w1b = wr4[1 * 16 + t * 2 + 1];
    const float4 w2a = wr4[2 * 16 + t * 2], w2b = wr4[2 * 16 + t * 2 + 1];
    const float4 bga = reinterpret_cast<const float4*>(b_s)[t * 2];
    const float4 bgb = reinterpret_cast<const float4*>(b_s)[t * 2 + 1];

    a0 = fmaf(r0, w0a.x, a0); a1 = fmaf(r0, w0a.y, a1);
    a2 = fmaf(r0, w0a.z, a2); a3 = fmaf(r0, w0a.w, a3);
    a4 = fmaf(r0, w0b.x, a4); a5 = fmaf(r0, w0b.y, a5);
    a6 = fmaf(r0, w0b.z, a6); a7 = fmaf(r0, w0b.w, a7);
    a0 = fmaf(r1, w1a.x, a0); a1 = fmaf(r1, w1a.y, a1);
    a2 = fmaf(r1, w1a.z, a2); a3 = fmaf(r1, w1a.w, a3);
    a4 = fmaf(r1, w1b.x, a4); a5 = fmaf(r1, w1b.y, a5);
    a6 = fmaf(r1, w1b.z, a6); a7 = fmaf(r1, w1b.w, a7);
    a0 = fmaf(r2, w2a.x, a0); a1 = fmaf(r2, w2a.y, a1);
    a2 = fmaf(r2, w2a.z, a2); a3 = fmaf(r2, w2a.w, a3);
    a4 = fmaf(r2, w2b.x, a4); a5 = fmaf(r2, w2b.y, a5);
    a6 = fmaf(r2, w2b.z, a6); a7 = fmaf(r2, w2b.w, a7);

    float4 resA, resB;
    resA.x = fmaxf(fmaf(a0, inv, bga.x), 0.0f);
    resA.y = fmaxf(fmaf(a1, inv, bga.y), 0.0f);
    resA.z = fmaxf(fmaf(a2, inv, bga.z), 0.0f);
    resA.w = fmaxf(fmaf(a3, inv, bga.w), 0.0f);
    resB.x = fmaxf(fmaf(a4, inv, bgb.x), 0.0f);
    resB.y = fmaxf(fmaf(a5, inv, bgb.y), 0.0f);
    resB.z = fmaxf(fmaf(a6, inv, bgb.z), 0.0f);
    resB.w = fmaxf(fmaf(a7, inv, bgb.w), 0.0f);

    float4* op = reinterpret_cast<float4*>(out) + (size_t)row * 16;
    op[t * 2]     = resA;
    op[t * 2 + 1] = resB;
}

extern "C" void kernel_launch(void* const* d_in, const int* in_sizes, int n_in,
                              void* d_out, int out_size)
{
    // metadata order: keys, points, feats, n_idxs, neighbor_rel,
    //                 neighbor_valid, W, b
    const float* feats  = (const float*)d_in[2];
    const int*   n_idxs = (const int*)  d_in[3];
    const float* nrel   = (const float*)d_in[4];
    const int*   nvalid = (const int*)  d_in[5];
    const float* W      = (const float*)d_in[6];
    const float* bias   = (const float*)d_in[7];
    float*       out    = (float*)d_out;

    const int rows_total = out_size / 64;   // 131072

    __half* pf = nullptr;
    cudaGetSymbolAddress((void**)&pf, g_pf);

    proj_kernel<<<TILES, 256>>>(feats, W, pf);

    // gather as PDL secondary: launch overlaps proj's tail
    const int grid = (rows_total + ROWS_PER_BLOCK - 1) / ROWS_PER_BLOCK;
    cudaLaunchConfig_t cfg = {};
    cfg.gridDim  = dim3(grid, 1, 1);
    cfg.blockDim = dim3(THREADS, 1, 1);
    cudaLaunchAttribute attrs[1];
    attrs[0].id = cudaLaunchAttributeProgrammaticStreamSerialization;
    attrs[0].val.programmaticStreamSerializationAllowed = 1;
    cfg.attrs = attrs;
    cfg.numAttrs = 1;
    cudaLaunchKernelEx(&cfg, gather_kernel, pf, n_idxs, nvalid, nrel,
                       W, bias, out, rows_total);
}